// round 1
// baseline (speedup 1.0000x reference)
#include <cuda_runtime.h>
#include <cstdint>
#include <cstddef>

#define BATCH  4096
#define INDIM  1024
#define DICT   16384
#define KHALF  32
#define MAXSEL 64

// ---------------- compact selection scratch (static __device__, no allocs) ---
__device__ int   g_nsel[BATCH];
__device__ int   g_idx [BATCH * MAXSEL];
__device__ float g_hu  [BATCH * MAXSEL];
__device__ float g_hc  [BATCH * MAXSEL];

// =====================================================================
// Encoder GEMM: C[M,N] = A[M,K] * B[K,N] + bias[N]
// M=4096, K=1024, N=16384.  fp32 CUDA-core, 128x128x16 tiles, 8x8/thread,
// double-buffered smem. Baseline for correctness; tensor-core split-precision
// comes in a later round.
// =====================================================================
#define BM  128
#define BN  128
#define BKK 16

__global__ void __launch_bounds__(256, 2)
sgemm_bias(const float* __restrict__ A, const float* __restrict__ B,
           const float* __restrict__ bias, float* __restrict__ C)
{
    const int K = INDIM, N = DICT;
    __shared__ float As[2][BKK][BM];
    __shared__ float Bs[2][BKK][BN];

    const int tid = threadIdx.x;
    const int tx  = tid & 15;
    const int ty  = tid >> 4;
    const int m0  = blockIdx.y * BM;
    const int n0  = blockIdx.x * BN;

    const float* Ab = A + (size_t)m0 * K;
    const float* Bb = B + n0;

    // per-thread load coordinates (each thread moves 2 float4 of A, 2 of B)
    const int aR = tid >> 2;            // 0..63 (second chunk: +64)
    const int aK = (tid & 3) << 2;      // 0,4,8,12
    const int bK = tid >> 5;            // 0..7  (second chunk: +8)
    const int bN = (tid & 31) << 2;     // 0..124

    float acc[8][8];
    #pragma unroll
    for (int i = 0; i < 8; i++)
        #pragma unroll
        for (int j = 0; j < 8; j++) acc[i][j] = 0.0f;

    // ---- prologue: tile 0 into buffer 0 ----
    {
        float4 a0 = *reinterpret_cast<const float4*>(Ab + (size_t)aR * K + aK);
        float4 a1 = *reinterpret_cast<const float4*>(Ab + (size_t)(aR + 64) * K + aK);
        float4 b0 = *reinterpret_cast<const float4*>(Bb + (size_t)bK * N + bN);
        float4 b1 = *reinterpret_cast<const float4*>(Bb + (size_t)(bK + 8) * N + bN);
        As[0][aK + 0][aR] = a0.x; As[0][aK + 1][aR] = a0.y;
        As[0][aK + 2][aR] = a0.z; As[0][aK + 3][aR] = a0.w;
        As[0][aK + 0][aR + 64] = a1.x; As[0][aK + 1][aR + 64] = a1.y;
        As[0][aK + 2][aR + 64] = a1.z; As[0][aK + 3][aR + 64] = a1.w;
        *reinterpret_cast<float4*>(&Bs[0][bK][bN])     = b0;
        *reinterpret_cast<float4*>(&Bs[0][bK + 8][bN]) = b1;
    }
    __syncthreads();

    const int nk = K / BKK;   // 64
    for (int t = 0; t < nk; t++) {
        const int buf = t & 1;
        float4 pa0, pa1, pb0, pb1;
        const bool more = (t + 1 < nk);
        if (more) {
            const int k0 = (t + 1) * BKK;
            pa0 = *reinterpret_cast<const float4*>(Ab + (size_t)aR * K + k0 + aK);
            pa1 = *reinterpret_cast<const float4*>(Ab + (size_t)(aR + 64) * K + k0 + aK);
            pb0 = *reinterpret_cast<const float4*>(Bb + (size_t)(k0 + bK) * N + bN);
            pb1 = *reinterpret_cast<const float4*>(Bb + (size_t)(k0 + bK + 8) * N + bN);
        }

        #pragma unroll
        for (int k = 0; k < BKK; k++) {
            float4 a0 = *reinterpret_cast<const float4*>(&As[buf][k][ty * 8]);
            float4 a1 = *reinterpret_cast<const float4*>(&As[buf][k][ty * 8 + 4]);
            float4 b0 = *reinterpret_cast<const float4*>(&Bs[buf][k][tx * 8]);
            float4 b1 = *reinterpret_cast<const float4*>(&Bs[buf][k][tx * 8 + 4]);
            float ra[8] = {a0.x, a0.y, a0.z, a0.w, a1.x, a1.y, a1.z, a1.w};
            float rb[8] = {b0.x, b0.y, b0.z, b0.w, b1.x, b1.y, b1.z, b1.w};
            #pragma unroll
            for (int i = 0; i < 8; i++)
                #pragma unroll
                for (int j = 0; j < 8; j++)
                    acc[i][j] += ra[i] * rb[j];
        }

        if (more) {
            const int wb = buf ^ 1;
            As[wb][aK + 0][aR] = pa0.x; As[wb][aK + 1][aR] = pa0.y;
            As[wb][aK + 2][aR] = pa0.z; As[wb][aK + 3][aR] = pa0.w;
            As[wb][aK + 0][aR + 64] = pa1.x; As[wb][aK + 1][aR + 64] = pa1.y;
            As[wb][aK + 2][aR + 64] = pa1.z; As[wb][aK + 3][aR + 64] = pa1.w;
            *reinterpret_cast<float4*>(&Bs[wb][bK][bN])     = pb0;
            *reinterpret_cast<float4*>(&Bs[wb][bK + 8][bN]) = pb1;
        }
        __syncthreads();
    }

    // ---- epilogue: C = acc + bias ----
    const float* bp = bias + n0 + tx * 8;
    float bb[8];
    #pragma unroll
    for (int j = 0; j < 8; j++) bb[j] = bp[j];
    #pragma unroll
    for (int i = 0; i < 8; i++) {
        const int row = m0 + ty * 8 + i;
        float* Cp = C + (size_t)row * N + n0 + tx * 8;
        float4 o0, o1;
        o0.x = acc[i][0] + bb[0]; o0.y = acc[i][1] + bb[1];
        o0.z = acc[i][2] + bb[2]; o0.w = acc[i][3] + bb[3];
        o1.x = acc[i][4] + bb[4]; o1.y = acc[i][5] + bb[5];
        o1.z = acc[i][6] + bb[6]; o1.w = acc[i][7] + bb[7];
        *reinterpret_cast<float4*>(Cp)     = o0;
        *reinterpret_cast<float4*>(Cp + 4) = o1;
    }
}

// =====================================================================
// Exact per-row top-32 via 8-bit radix select (monotone float->uint keys).
// Ties broken by smallest index (matches jax.lax.top_k stable ordering).
// =====================================================================
__device__ __forceinline__ unsigned fkey(float f)
{
    unsigned u = __float_as_uint(f);
    return (u & 0x80000000u) ? ~u : (u | 0x80000000u);
}

struct TopkShared {
    unsigned hist[256];
    int      ngt, neq;
    int      eqbuf[64];
    unsigned sprefix;
    int      sneed;
    int      ulist[KHALF];
    int      clist[KHALF];
    int      cnt;
};

__device__ void select_top32(const float* __restrict__ rowp, int* outlist, TopkShared* s)
{
    const int tid = threadIdx.x;
    unsigned prefix = 0, pmask = 0;
    int need = KHALF;

    for (int shift = 24; shift >= 0; shift -= 8) {
        s->hist[tid] = 0;
        __syncthreads();
        for (int i = tid; i < DICT; i += 256) {
            unsigned k = fkey(rowp[i]);
            if ((k & pmask) == prefix)
                atomicAdd(&s->hist[(k >> shift) & 255], 1u);
        }
        __syncthreads();
        if (tid == 0) {
            int cum = 0;
            int b = 255;
            for (; b > 0; b--) {
                int c = (int)s->hist[b];
                if (cum + c >= need) break;
                cum += c;
            }
            s->sprefix = prefix | ((unsigned)b << shift);
            s->sneed   = need - cum;
        }
        __syncthreads();
        prefix = s->sprefix;
        need   = s->sneed;
        pmask |= (0xFFu << shift);
        __syncthreads();
    }

    // prefix == key of the 32nd-largest; take (KHALF-need) strictly-greater
    // plus `need` equal keys at smallest indices.
    if (tid == 0) { s->ngt = 0; s->neq = 0; }
    __syncthreads();
    const unsigned thr = prefix;
    for (int i = tid; i < DICT; i += 256) {
        unsigned k = fkey(rowp[i]);
        if (k > thr) {
            int p = atomicAdd(&s->ngt, 1);
            outlist[p] = i;
        } else if (k == thr) {
            int p = atomicAdd(&s->neq, 1);
            if (p < 64) s->eqbuf[p] = i;
        }
    }
    __syncthreads();
    if (tid == 0) {
        int base = s->ngt;                    // == KHALF - need
        int ne = s->neq; if (ne > 64) ne = 64;
        for (int a = 1; a < ne; a++) {        // ascending insertion sort (tiny)
            int v = s->eqbuf[a]; int b = a - 1;
            while (b >= 0 && s->eqbuf[b] > v) { s->eqbuf[b + 1] = s->eqbuf[b]; b--; }
            s->eqbuf[b + 1] = v;
        }
        for (int q = 0; q < need; q++) outlist[base + q] = s->eqbuf[q];
    }
    __syncthreads();
}

__global__ void __launch_bounds__(256)
topk_kernel(const float* __restrict__ Hu, const float* __restrict__ Hc)
{
    __shared__ TopkShared s;
    const int row = blockIdx.x;
    const int tid = threadIdx.x;
    const float* ru = Hu + (size_t)row * DICT;
    const float* rc = Hc + (size_t)row * DICT;

    select_top32(ru, s.ulist, &s);
    select_top32(rc, s.clist, &s);

    if (tid == 0) s.cnt = KHALF;
    __syncthreads();

    if (tid < KHALF) {
        int idx = s.ulist[tid];
        g_idx[row * MAXSEL + tid] = idx;
        g_hu [row * MAXSEL + tid] = ru[idx];
        g_hc [row * MAXSEL + tid] = rc[idx];
    }
    if (tid < KHALF) {
        int idx = s.clist[tid];
        bool dup = false;
        for (int q = 0; q < KHALF; q++) dup |= (s.ulist[q] == idx);
        if (!dup) {
            int p = atomicAdd(&s.cnt, 1);
            g_idx[row * MAXSEL + p] = idx;
            g_hu [row * MAXSEL + p] = ru[idx];
            g_hc [row * MAXSEL + p] = rc[idx];
        }
    }
    __syncthreads();
    if (tid == 0) g_nsel[row] = s.cnt;
}

// =====================================================================
// zero-fill z_u / z_c / mask (contiguous region), then scatter selected.
// =====================================================================
__global__ void fill_zero(float4* __restrict__ p, size_t n4)
{
    size_t i = (size_t)blockIdx.x * blockDim.x + threadIdx.x;
    size_t stride = (size_t)gridDim.x * blockDim.x;
    float4 z = make_float4(0.f, 0.f, 0.f, 0.f);
    for (; i < n4; i += stride) p[i] = z;
}

__global__ void scatter_kernel(float* __restrict__ zu, float* __restrict__ zc,
                               float* __restrict__ mk)
{
    const int row = blockIdx.x;
    const int s   = threadIdx.x;
    if (s < g_nsel[row]) {
        const int idx = g_idx[row * MAXSEL + s];
        const size_t o = (size_t)row * DICT + idx;
        mk[o] = 1.0f;
        zu[o] = fmaxf(g_hu[row * MAXSEL + s], 0.f);
        zc[o] = fmaxf(g_hc[row * MAXSEL + s], 0.f);
    }
}

// =====================================================================
// Sparse decode: per row, gather <=64 W_dec rows once, produce both the
// "same" and "cross" outputs for that decoder.
//   A_is_u=1: Wd=W_dec_u, outA=x_u_hat (coef z_u), outB=x_u_cross (coef z_c)
//   A_is_u=0: Wd=W_dec_c, outA=x_c_hat (coef z_c), outB=x_c_cross (coef z_u)
// =====================================================================
__global__ void __launch_bounds__(256)
decode_kernel(const float* __restrict__ Wd, float* __restrict__ outA,
              float* __restrict__ outB, int A_is_u)
{
    __shared__ int   sn;
    __shared__ int   sidx[MAXSEL];
    __shared__ float ca[MAXSEL], cb[MAXSEL];
    const int row = blockIdx.x;
    const int tid = threadIdx.x;

    if (tid == 0) sn = g_nsel[row];
    if (tid < MAXSEL) {
        sidx[tid] = g_idx[row * MAXSEL + tid];
        float zu = fmaxf(g_hu[row * MAXSEL + tid], 0.f);
        float zc = fmaxf(g_hc[row * MAXSEL + tid], 0.f);
        ca[tid] = A_is_u ? zu : zc;
        cb[tid] = A_is_u ? zc : zu;
    }
    __syncthreads();

    float4 a = make_float4(0.f, 0.f, 0.f, 0.f);
    float4 b = make_float4(0.f, 0.f, 0.f, 0.f);
    const int n = sn;
    #pragma unroll 4
    for (int s = 0; s < n; s++) {
        const float4 w = *reinterpret_cast<const float4*>(
            Wd + (size_t)sidx[s] * INDIM + tid * 4);
        const float fa = ca[s], fb = cb[s];
        a.x += fa * w.x; a.y += fa * w.y; a.z += fa * w.z; a.w += fa * w.w;
        b.x += fb * w.x; b.y += fb * w.y; b.z += fb * w.z; b.w += fb * w.w;
    }
    const size_t o = (size_t)row * INDIM + tid * 4;
    *reinterpret_cast<float4*>(outA + o) = a;
    *reinterpret_cast<float4*>(outB + o) = b;
}

// =====================================================================
// launch
// =====================================================================
extern "C" void kernel_launch(void* const* d_in, const int* in_sizes, int n_in,
                              void* d_out, int out_size)
{
    const float* x_u     = (const float*)d_in[0];
    const float* x_c     = (const float*)d_in[1];
    const float* W_enc_u = (const float*)d_in[2];
    const float* b_enc_u = (const float*)d_in[3];
    const float* W_enc_c = (const float*)d_in[4];
    const float* b_enc_c = (const float*)d_in[5];
    const float* W_dec_u = (const float*)d_in[6];
    const float* W_dec_c = (const float*)d_in[7];

    float* out = (float*)d_out;
    const size_t ZN = (size_t)BATCH * DICT;       // 67,108,864
    const size_t XN = (size_t)BATCH * INDIM;      //  4,194,304
    float* z_u  = out;
    float* z_c  = out + ZN;
    float* mk   = out + 2 * ZN;
    float* xuh  = out + 3 * ZN;
    float* xch  = xuh + XN;
    float* xuc  = xch + XN;
    float* xcc  = xuc + XN;

    dim3 gemm_grid(DICT / BN, BATCH / BM);        // 128 x 32

    // h_u / h_c are staged in the z_u / z_c output regions (read by topk,
    // then overwritten by fill+scatter).
    sgemm_bias<<<gemm_grid, 256>>>(x_u, W_enc_u, b_enc_u, z_u);
    sgemm_bias<<<gemm_grid, 256>>>(x_c, W_enc_c, b_enc_c, z_c);

    topk_kernel<<<BATCH, 256>>>(z_u, z_c);

    fill_zero<<<8192, 256>>>((float4*)out, (3 * ZN) / 4);

    scatter_kernel<<<BATCH, MAXSEL>>>(z_u, z_c, mk);

    decode_kernel<<<BATCH, 256>>>(W_dec_u, xuh, xuc, 1);
    decode_kernel<<<BATCH, 256>>>(W_dec_c, xch, xcc, 0);
}